// round 1
// baseline (speedup 1.0000x reference)
#include <cuda_runtime.h>

// ============================================================================
// AdderNet TauNet: per-row (256 floats) -> (tau_amp, tau_inten)
// Strategy: setup kernel quantizes weights + folds BN; main kernel is
// warp-per-element with shared-memory activation staging.
// ============================================================================

#define EPSV 1e-5f

// ---- device global scratch (allocation-free) ----
// small weights packed region (float, 16B-aligned rows):
//   W1: 5  x16  (pre1, 13 used)          @ 0    (80)
//   W2: 50 x12  (pre2, [c*5+ci][12], 9 used) @ 80 (600)
//   R1: 10 x12  (10 used)                @ 680 (120)
//   R2: 10 x12                           @ 800 (120)
#define W1OFF 0
#define W2OFF 80
#define R1OFF 680
#define R2OFF 800
#define SMALL_N 920
__device__ float g_small[928];

// big o-layer weights, packed-transposed [branch][i/4][c][4]
__device__ float g_qoa[2 * 35 * 70 * 4];   // 19600
__device__ float g_qob[2 * 18 * 30 * 4];   // 4320 (i padded 70->72 with 0)
__device__ float g_qoc[64];                // [branch*32 + i], i>=30 zero

// folded BN: y_bn = alpha * y + beta
__device__ float g_a1[5],   g_b1[5];
__device__ float g_a2[10],  g_b2[10];
__device__ float g_ar1[10], g_br1[10];
__device__ float g_ar2[10], g_br2[10];
__device__ float g_aoa[140], g_boa[140];   // [0:70) o1a, [70:140) o2a
__device__ float g_aob[60],  g_bob[60];    // [0:30) o1b, [30:60) o2b
__device__ float g_aoc[2],   g_boc[2];

__device__ __forceinline__ float quantv(float w, float s) {
    float t = fminf(fmaxf(w / s, -127.f), 127.f);
    return rintf(t) * s;   // rintf = round-half-to-even, matches jnp.round
}

__device__ __forceinline__ void fill_bn(const float* bn, int c, float* A, float* Bt) {
    for (int i = threadIdx.x; i < c; i += blockDim.x) {
        float g = bn[i], b = bn[c + i], m = bn[2 * c + i], v = bn[3 * c + i];
        float al = g * rsqrtf(v + EPSV);
        A[i] = al;
        Bt[i] = b - m * al;
    }
}

// ---------------------------------------------------------------------------
// Setup: quantize weights into packed layouts, fold BN. grid = 11 blocks.
// ---------------------------------------------------------------------------
__global__ void setup_kernel(
    const float* __restrict__ w1,   const float* __restrict__ w2,
    const float* __restrict__ wr1,  const float* __restrict__ wr2,
    const float* __restrict__ wo1a, const float* __restrict__ wo1b, const float* __restrict__ wo1c,
    const float* __restrict__ wo2a, const float* __restrict__ wo2b, const float* __restrict__ wo2c,
    const float* __restrict__ bn1,  const float* __restrict__ bn2,
    const float* __restrict__ bnr1, const float* __restrict__ bnr2,
    const float* __restrict__ bno1a, const float* __restrict__ bno1b, const float* __restrict__ bno1c,
    const float* __restrict__ bno2a, const float* __restrict__ bno2b, const float* __restrict__ bno2c)
{
    const int blk = blockIdx.x, tid = threadIdx.x;
    if (blk < 10) {
        const float* w; int n;
        switch (blk) {
            case 0: w = w1;   n = 65;   break;
            case 1: w = w2;   n = 450;  break;
            case 2: w = wr1;  n = 100;  break;
            case 3: w = wr2;  n = 100;  break;
            case 4: w = wo1a; n = 9800; break;
            case 5: w = wo2a; n = 9800; break;
            case 6: w = wo1b; n = 2100; break;
            case 7: w = wo2b; n = 2100; break;
            case 8: w = wo1c; n = 30;   break;
            default: w = wo2c; n = 30;  break;
        }
        __shared__ float red[256];
        float m = 0.f;
        for (int i = tid; i < n; i += 256) m = fmaxf(m, fabsf(w[i]));
        red[tid] = m;
        __syncthreads();
        for (int s = 128; s > 0; s >>= 1) {
            if (tid < s) red[tid] = fmaxf(red[tid], red[tid + s]);
            __syncthreads();
        }
        const float s = red[0] / 127.f;

        if (blk == 0) {
            for (int j = tid; j < 80; j += 256) {
                int c = j >> 4, k = j & 15;
                g_small[W1OFF + j] = (k < 13) ? quantv(w[c * 13 + k], s) : 0.f;
            }
        } else if (blk == 1) {
            for (int j = tid; j < 600; j += 256) {
                int row = j / 12, k = j - row * 12;    // row = c*5+ci
                g_small[W2OFF + j] = (k < 9) ? quantv(w[row * 9 + k], s) : 0.f;
            }
        } else if (blk == 2 || blk == 3) {
            float* dst = g_small + (blk == 2 ? R1OFF : R2OFF);
            for (int j = tid; j < 120; j += 256) {
                int c = j / 12, k = j - c * 12;
                dst[j] = (k < 10) ? quantv(w[c * 10 + k], s) : 0.f;
            }
        } else if (blk == 4 || blk == 5) {
            float* dst = g_qoa + (blk - 4) * 9800;
            for (int j = tid; j < 9800; j += 256) {
                int i4 = j / 280, rem = j - i4 * 280;
                int c = rem >> 2, t = rem & 3;
                dst[j] = quantv(w[c * 140 + i4 * 4 + t], s);
            }
        } else if (blk == 6 || blk == 7) {
            float* dst = g_qob + (blk - 6) * 2160;
            for (int j = tid; j < 2160; j += 256) {
                int i4 = j / 120, rem = j - i4 * 120;
                int c = rem >> 2, t = rem & 3;
                int i = i4 * 4 + t;
                dst[j] = (i < 70) ? quantv(w[c * 70 + i], s) : 0.f;
            }
        } else {
            float* dst = g_qoc + (blk - 8) * 32;
            if (tid < 32) dst[tid] = (tid < 30) ? quantv(w[tid], s) : 0.f;
        }
    } else {
        fill_bn(bn1, 5,  g_a1,  g_b1);
        fill_bn(bn2, 10, g_a2,  g_b2);
        fill_bn(bnr1, 10, g_ar1, g_br1);
        fill_bn(bnr2, 10, g_ar2, g_br2);
        fill_bn(bno1a, 70, g_aoa,      g_boa);
        fill_bn(bno2a, 70, g_aoa + 70, g_boa + 70);
        fill_bn(bno1b, 30, g_aob,      g_bob);
        fill_bn(bno2b, 30, g_aob + 30, g_bob + 30);
        fill_bn(bno1c, 1, g_aoc,     g_boc);
        fill_bn(bno2c, 1, g_aoc + 1, g_boc + 1);
    }
}

// ---------------------------------------------------------------------------
// Main kernel: one warp per element (strided loop), 8 warps/CTA.
// ---------------------------------------------------------------------------
__device__ __forceinline__ void ld4(float* d, const float* s) {
    float4 v = *(const float4*)s;
    d[0] = v.x; d[1] = v.y; d[2] = v.z; d[3] = v.w;
}

__global__ void __launch_bounds__(256) taunet_main(const float* __restrict__ x,
                                                   float* __restrict__ out, int nB)
{
    __shared__ __align__(16) float s_small[SMALL_N];
    __shared__ __align__(16) float s_x [8][256];
    __shared__ __align__(16) float s_h1[8][256];   // stride-50 rows (5 ch x 49 pos)
    __shared__ __align__(16) float s_h2[8][144];
    __shared__ __align__(16) float s_t [8][144];
    __shared__ __align__(16) float s_f [8][144];
    __shared__ __align__(16) float s_a [8][144];   // [branch*72 + c], pads zero
    __shared__ __align__(16) float s_b [8][64];    // [branch*32 + c], pads zero

    for (int i = threadIdx.x; i < SMALL_N; i += 256) s_small[i] = g_small[i];
    __syncthreads();

    const int warp = threadIdx.x >> 5, lane = threadIdx.x & 31;
    float* bx  = s_x[warp];
    float* bh1 = s_h1[warp];
    float* bh2 = s_h2[warp];
    float* bt  = s_t[warp];
    float* bf  = s_f[warp];
    float* ba  = s_a[warp];
    float* bb  = s_b[warp];

    // ---- per-lane o-layer slot precompute (element-independent) ----
    // oa: channels j = lane, lane+32, lane+64, lane+96, min(lane+128,139)
    //     branch = j/70, c = j%70; weight float4 index = branch*2450 + c (+ i4*70)
    const int j2 = lane + 64, j3 = lane + 96;
    const int j4 = (lane + 128 < 140) ? lane + 128 : 139;
    const int oa0 = lane;
    const int oa1 = lane + 32;
    const int oa2 = (j2 < 70) ? j2 : (2450 + (j2 - 70));
    const int oa3 = 2450 + (j3 - 70);
    const int oa4 = 2450 + (j4 - 70);
    const int d2 = (j2 < 70) ? j2 : (72 + (j2 - 70));
    const int d3 = 72 + (j3 - 70);
    const int d4 = 72 + (j4 - 70);
    // ob: channels j = lane, min(lane+32, 59); branch = j/30
    const int jb1 = (lane + 32 < 60) ? lane + 32 : 59;
    const int obb0 = lane / 30, obc0 = lane - 30 * obb0;
    const int ob0 = obb0 * 540 + obc0;
    const int ob1 = 540 + (jb1 - 30);

    const int gw = blockIdx.x * 8 + warp;
    const int stride = gridDim.x * 8;

    for (int e = gw; e < nB; e += stride) {
        // ---- load input row (coalesced) ----
        const float* xe = x + (size_t)e * 256;
        #pragma unroll
        for (int i = 0; i < 8; i++) bx[lane + 32 * i] = __ldg(xe + lane + 32 * i);
        __syncwarp();

        // ---- pre1: 5ch x 49pos, K=13, stride 5 ----
        #pragma unroll 1
        for (int r = 0; r < 8; r++) {
            int idx = lane + 32 * r;
            if (idx < 245) {
                int c = idx / 49, p = idx - 49 * c;
                float w[16];
                const float* wb = s_small + W1OFF + c * 16;
                ld4(w, wb); ld4(w + 4, wb + 4); ld4(w + 8, wb + 8); ld4(w + 12, wb + 12);
                const float* xp = bx + 5 * p;
                float acc = 0.f;
                #pragma unroll
                for (int k = 0; k < 13; k++) acc += fabsf(xp[k] - w[k]);
                float al = __ldg(g_a1 + c), be = __ldg(g_b1 + c);
                bh1[c * 50 + p] = fmaxf(fmaf(-acc, al, be), 0.f);
            }
        }
        __syncwarp();

        // ---- pre2: 10ch x 14pos, 5cin x K=9, stride 3 ----
        #pragma unroll 1
        for (int r = 0; r < 5; r++) {
            int idx = lane + 32 * r;
            if (idx < 140) {
                int c = idx / 14, p = idx - 14 * c;
                const float* hp = bh1 + 3 * p;
                float acc = 0.f;
                #pragma unroll
                for (int ci = 0; ci < 5; ci++) {
                    float w[12];
                    const float* wb = s_small + W2OFF + (c * 5 + ci) * 12;
                    ld4(w, wb); ld4(w + 4, wb + 4); ld4(w + 8, wb + 8);
                    const float* hc = hp + ci * 50;
                    #pragma unroll
                    for (int k = 0; k < 9; k++) acc += fabsf(hc[k] - w[k]);
                }
                float al = __ldg(g_a2 + c), be = __ldg(g_b2 + c);
                bh2[c * 14 + p] = fmaxf(fmaf(-acc, al, be), 0.f);
            }
        }
        __syncwarp();

        // ---- r1: 10->10, 1x1 ----
        #pragma unroll 1
        for (int r = 0; r < 5; r++) {
            int idx = lane + 32 * r;
            if (idx < 140) {
                int c = idx / 14, p = idx - 14 * c;
                float w[12];
                const float* wb = s_small + R1OFF + c * 12;
                ld4(w, wb); ld4(w + 4, wb + 4); ld4(w + 8, wb + 8);
                float acc = 0.f;
                #pragma unroll
                for (int ci = 0; ci < 10; ci++) acc += fabsf(bh2[ci * 14 + p] - w[ci]);
                float al = __ldg(g_ar1 + c), be = __ldg(g_br1 + c);
                bt[c * 14 + p] = fmaxf(fmaf(-acc, al, be), 0.f);
            }
        }
        __syncwarp();

        // ---- r2 + residual: f = relu(bn(r2(t)) + h2) ----
        #pragma unroll 1
        for (int r = 0; r < 5; r++) {
            int idx = lane + 32 * r;
            if (idx < 140) {
                int c = idx / 14, p = idx - 14 * c;
                float w[12];
                const float* wb = s_small + R2OFF + c * 12;
                ld4(w, wb); ld4(w + 4, wb + 4); ld4(w + 8, wb + 8);
                float acc = 0.f;
                #pragma unroll
                for (int ci = 0; ci < 10; ci++) acc += fabsf(bt[ci * 14 + p] - w[ci]);
                float al = __ldg(g_ar2 + c), be = __ldg(g_br2 + c);
                float u = fmaf(-acc, al, be);
                bf[c * 14 + p] = fmaxf(u + bh2[c * 14 + p], 0.f);
            }
        }
        __syncwarp();

        // ---- oa: both branches fused, 140 channels over 5 lane-slots ----
        {
            float acc0 = 0.f, acc1 = 0.f, acc2 = 0.f, acc3 = 0.f, acc4 = 0.f;
            const float4* QA = (const float4*)g_qoa;
            #pragma unroll 5
            for (int i4 = 0; i4 < 35; i4++) {
                float4 fv = *(const float4*)(bf + 4 * i4);
                int row = i4 * 70;
                float4 w;
                w = __ldg(QA + row + oa0);
                acc0 += (fabsf(fv.x - w.x) + fabsf(fv.y - w.y)) + (fabsf(fv.z - w.z) + fabsf(fv.w - w.w));
                w = __ldg(QA + row + oa1);
                acc1 += (fabsf(fv.x - w.x) + fabsf(fv.y - w.y)) + (fabsf(fv.z - w.z) + fabsf(fv.w - w.w));
                w = __ldg(QA + row + oa2);
                acc2 += (fabsf(fv.x - w.x) + fabsf(fv.y - w.y)) + (fabsf(fv.z - w.z) + fabsf(fv.w - w.w));
                w = __ldg(QA + row + oa3);
                acc3 += (fabsf(fv.x - w.x) + fabsf(fv.y - w.y)) + (fabsf(fv.z - w.z) + fabsf(fv.w - w.w));
                w = __ldg(QA + row + oa4);
                acc4 += (fabsf(fv.x - w.x) + fabsf(fv.y - w.y)) + (fabsf(fv.z - w.z) + fabsf(fv.w - w.w));
            }
            ba[lane]      = fmaxf(fmaf(-acc0, __ldg(g_aoa + lane),      __ldg(g_boa + lane)), 0.f);
            ba[lane + 32] = fmaxf(fmaf(-acc1, __ldg(g_aoa + lane + 32), __ldg(g_boa + lane + 32)), 0.f);
            ba[d2]        = fmaxf(fmaf(-acc2, __ldg(g_aoa + j2),        __ldg(g_boa + j2)), 0.f);
            ba[d3]        = fmaxf(fmaf(-acc3, __ldg(g_aoa + j3),        __ldg(g_boa + j3)), 0.f);
            ba[d4]        = fmaxf(fmaf(-acc4, __ldg(g_aoa + j4),        __ldg(g_boa + j4)), 0.f);
            if (lane < 2) { ba[70 + lane] = 0.f; ba[142 + lane] = 0.f; }
        }
        __syncwarp();

        // ---- ob: both branches, 60 channels over 2 lane-slots ----
        {
            float acc0 = 0.f, acc1 = 0.f;
            const float4* QB = (const float4*)g_qob;
            const float* a0p = ba + obb0 * 72;
            const float* a1p = ba + 72;
            #pragma unroll 6
            for (int i4 = 0; i4 < 18; i4++) {
                float4 av0 = *(const float4*)(a0p + 4 * i4);
                float4 av1 = *(const float4*)(a1p + 4 * i4);
                int row = i4 * 30;
                float4 w;
                w = __ldg(QB + row + ob0);
                acc0 += (fabsf(av0.x - w.x) + fabsf(av0.y - w.y)) + (fabsf(av0.z - w.z) + fabsf(av0.w - w.w));
                w = __ldg(QB + row + ob1);
                acc1 += (fabsf(av1.x - w.x) + fabsf(av1.y - w.y)) + (fabsf(av1.z - w.z) + fabsf(av1.w - w.w));
            }
            bb[obb0 * 32 + obc0]  = fmaxf(fmaf(-acc0, __ldg(g_aob + lane), __ldg(g_bob + lane)), 0.f);
            bb[32 + (jb1 - 30)]   = fmaxf(fmaf(-acc1, __ldg(g_aob + jb1),  __ldg(g_bob + jb1)), 0.f);
            if (lane < 2) { bb[30 + lane] = 0.f; bb[62 + lane] = 0.f; }
        }
        __syncwarp();

        // ---- oc: two 30-tap reductions (padded to 32, pads are |0-0|=0) ----
        {
            float v0 = fabsf(bb[lane]      - __ldg(g_qoc + lane));
            float v1 = fabsf(bb[32 + lane] - __ldg(g_qoc + 32 + lane));
            #pragma unroll
            for (int s = 16; s > 0; s >>= 1) {
                v0 += __shfl_xor_sync(0xffffffffu, v0, s);
                v1 += __shfl_xor_sync(0xffffffffu, v1, s);
            }
            if (lane == 0) {
                out[e]      = fmaxf(fmaf(-v0, g_aoc[0], g_boc[0]), 0.f);
                out[nB + e] = fmaxf(fmaf(-v1, g_aoc[1], g_boc[1]), 0.f);
            }
        }
        __syncwarp();
    }
}

// ---------------------------------------------------------------------------
extern "C" void kernel_launch(void* const* d_in, const int* in_sizes, int n_in,
                              void* d_out, int out_size)
{
    const float* x     = (const float*)d_in[0];
    const float* w1    = (const float*)d_in[1];
    const float* bn1   = (const float*)d_in[2];
    const float* w2    = (const float*)d_in[3];
    const float* bn2   = (const float*)d_in[4];
    const float* wr1   = (const float*)d_in[5];
    const float* bnr1  = (const float*)d_in[6];
    const float* wr2   = (const float*)d_in[7];
    const float* bnr2  = (const float*)d_in[8];
    const float* wo1a  = (const float*)d_in[9];
    const float* bno1a = (const float*)d_in[10];
    const float* wo1b  = (const float*)d_in[11];
    const float* bno1b = (const float*)d_in[12];
    const float* wo1c  = (const float*)d_in[13];
    const float* bno1c = (const float*)d_in[14];
    const float* wo2a  = (const float*)d_in[15];
    const float* bno2a = (const float*)d_in[16];
    const float* wo2b  = (const float*)d_in[17];
    const float* bno2b = (const float*)d_in[18];
    const float* wo2c  = (const float*)d_in[19];
    const float* bno2c = (const float*)d_in[20];

    const int nB = in_sizes[0] / 256;

    setup_kernel<<<11, 256>>>(w1, w2, wr1, wr2, wo1a, wo1b, wo1c, wo2a, wo2b, wo2c,
                              bn1, bn2, bnr1, bnr2, bno1a, bno1b, bno1c,
                              bno2a, bno2b, bno2c);
    taunet_main<<<256, 256>>>(x, (float*)d_out, nB);
}

// round 2
// speedup vs baseline: 2.1333x; 2.1333x over previous
#include <cuda_runtime.h>

// ============================================================================
// AdderNet TauNet: per-row (256 floats) -> (tau_amp, tau_inten)
// R2: pair-of-elements per warp (weight L1 reuse x2), smem aliasing, 512 CTAs.
// ============================================================================

#define EPSV 1e-5f

// ---- packed small weights ----
#define W1OFF 0
#define W2OFF 80
#define R1OFF 680
#define R2OFF 800
#define SMALL_N 920
__device__ float g_small[928];

// big o-layer weights, packed-transposed [branch][i/4][c][4]
__device__ float g_qoa[2 * 35 * 70 * 4];   // 19600
__device__ float g_qob[2 * 18 * 30 * 4];   // 4320
__device__ float g_qoc[64];

// folded BN
__device__ float g_a1[5],   g_b1[5];
__device__ float g_a2[10],  g_b2[10];
__device__ float g_ar1[10], g_br1[10];
__device__ float g_ar2[10], g_br2[10];
__device__ float g_aoa[140], g_boa[140];
__device__ float g_aob[60],  g_bob[60];
__device__ float g_aoc[2],   g_boc[2];

__device__ __forceinline__ float quantv(float w, float s) {
    float t = fminf(fmaxf(w / s, -127.f), 127.f);
    return rintf(t) * s;
}

__device__ __forceinline__ void fill_bn(const float* bn, int c, float* A, float* Bt) {
    for (int i = threadIdx.x; i < c; i += blockDim.x) {
        float g = bn[i], b = bn[c + i], m = bn[2 * c + i], v = bn[3 * c + i];
        float al = g * rsqrtf(v + EPSV);
        A[i] = al;
        Bt[i] = b - m * al;
    }
}

// ---------------------------------------------------------------------------
__global__ void setup_kernel(
    const float* __restrict__ w1,   const float* __restrict__ w2,
    const float* __restrict__ wr1,  const float* __restrict__ wr2,
    const float* __restrict__ wo1a, const float* __restrict__ wo1b, const float* __restrict__ wo1c,
    const float* __restrict__ wo2a, const float* __restrict__ wo2b, const float* __restrict__ wo2c,
    const float* __restrict__ bn1,  const float* __restrict__ bn2,
    const float* __restrict__ bnr1, const float* __restrict__ bnr2,
    const float* __restrict__ bno1a, const float* __restrict__ bno1b, const float* __restrict__ bno1c,
    const float* __restrict__ bno2a, const float* __restrict__ bno2b, const float* __restrict__ bno2c)
{
    const int blk = blockIdx.x, tid = threadIdx.x;
    if (blk < 10) {
        const float* w; int n;
        switch (blk) {
            case 0: w = w1;   n = 65;   break;
            case 1: w = w2;   n = 450;  break;
            case 2: w = wr1;  n = 100;  break;
            case 3: w = wr2;  n = 100;  break;
            case 4: w = wo1a; n = 9800; break;
            case 5: w = wo2a; n = 9800; break;
            case 6: w = wo1b; n = 2100; break;
            case 7: w = wo2b; n = 2100; break;
            case 8: w = wo1c; n = 30;   break;
            default: w = wo2c; n = 30;  break;
        }
        __shared__ float red[256];
        float m = 0.f;
        for (int i = tid; i < n; i += 256) m = fmaxf(m, fabsf(w[i]));
        red[tid] = m;
        __syncthreads();
        for (int s = 128; s > 0; s >>= 1) {
            if (tid < s) red[tid] = fmaxf(red[tid], red[tid + s]);
            __syncthreads();
        }
        const float s = red[0] / 127.f;

        if (blk == 0) {
            for (int j = tid; j < 80; j += 256) {
                int c = j >> 4, k = j & 15;
                g_small[W1OFF + j] = (k < 13) ? quantv(w[c * 13 + k], s) : 0.f;
            }
        } else if (blk == 1) {
            for (int j = tid; j < 600; j += 256) {
                int row = j / 12, k = j - row * 12;
                g_small[W2OFF + j] = (k < 9) ? quantv(w[row * 9 + k], s) : 0.f;
            }
        } else if (blk == 2 || blk == 3) {
            float* dst = g_small + (blk == 2 ? R1OFF : R2OFF);
            for (int j = tid; j < 120; j += 256) {
                int c = j / 12, k = j - c * 12;
                dst[j] = (k < 10) ? quantv(w[c * 10 + k], s) : 0.f;
            }
        } else if (blk == 4 || blk == 5) {
            float* dst = g_qoa + (blk - 4) * 9800;
            for (int j = tid; j < 9800; j += 256) {
                int i4 = j / 280, rem = j - i4 * 280;
                int c = rem >> 2, t = rem & 3;
                dst[j] = quantv(w[c * 140 + i4 * 4 + t], s);
            }
        } else if (blk == 6 || blk == 7) {
            float* dst = g_qob + (blk - 6) * 2160;
            for (int j = tid; j < 2160; j += 256) {
                int i4 = j / 120, rem = j - i4 * 120;
                int c = rem >> 2, t = rem & 3;
                int i = i4 * 4 + t;
                dst[j] = (i < 70) ? quantv(w[c * 70 + i], s) : 0.f;
            }
        } else {
            float* dst = g_qoc + (blk - 8) * 32;
            if (tid < 32) dst[tid] = (tid < 30) ? quantv(w[tid], s) : 0.f;
        }
    } else {
        fill_bn(bn1, 5,  g_a1,  g_b1);
        fill_bn(bn2, 10, g_a2,  g_b2);
        fill_bn(bnr1, 10, g_ar1, g_br1);
        fill_bn(bnr2, 10, g_ar2, g_br2);
        fill_bn(bno1a, 70, g_aoa,      g_boa);
        fill_bn(bno2a, 70, g_aoa + 70, g_boa + 70);
        fill_bn(bno1b, 30, g_aob,      g_bob);
        fill_bn(bno2b, 30, g_aob + 30, g_bob + 30);
        fill_bn(bno1c, 1, g_aoc,     g_boc);
        fill_bn(bno2c, 1, g_aoc + 1, g_boc + 1);
    }
}

// ---------------------------------------------------------------------------
// Per-warp scratch layout (floats), heavy aliasing of dead regions:
//   [0:256)   x, then t (r1 out), then a0 (oa out, 144)
//   [144:288) a1 (overlaps end of x/t + start of h1 -- both dead by oa)
//   [256:512) h1 (250 used), then b0 @288 (64), b1 @352 (64)
//   [512:656) h2
//   [656:800) f0
//   [800:944) f1
#define WS_N  944
#define XOFF  0
#define H1OFF 256
#define H2OFF 512
#define F0OFF 656
#define F1OFF 800
#define A0OFF 0
#define A1OFF 144
#define B0OFF 288
#define B1OFF 352

__device__ __forceinline__ void ld4(float* d, const float* s) {
    float4 v = *(const float4*)s;
    d[0] = v.x; d[1] = v.y; d[2] = v.z; d[3] = v.w;
}

__device__ __forceinline__ float l1d4(float4 a, float4 w) {
    return (fabsf(a.x - w.x) + fabsf(a.y - w.y)) + (fabsf(a.z - w.z) + fabsf(a.w - w.w));
}

// early phase: x row -> f (144 floats: 10ch x 14pos, stride 14, pads beyond 140 unused)
__device__ __forceinline__ void early_phase(const float* __restrict__ xe,
                                            float* ws, float* fout,
                                            const float* s_small, int lane)
{
    float* bx  = ws + XOFF;
    float* bh1 = ws + H1OFF;
    float* bh2 = ws + H2OFF;
    float* bt  = ws + XOFF;   // aliases x (dead after pre1)

    #pragma unroll
    for (int i = 0; i < 8; i++) bx[lane + 32 * i] = xe[lane + 32 * i];
    __syncwarp();

    // pre1: 5ch x 49pos, K=13, stride 5
    #pragma unroll 1
    for (int r = 0; r < 8; r++) {
        int idx = lane + 32 * r;
        if (idx < 245) {
            int c = idx / 49, p = idx - 49 * c;
            float w[16];
            const float* wb = s_small + W1OFF + c * 16;
            ld4(w, wb); ld4(w + 4, wb + 4); ld4(w + 8, wb + 8); ld4(w + 12, wb + 12);
            const float* xp = bx + 5 * p;
            float acc = 0.f;
            #pragma unroll
            for (int k = 0; k < 13; k++) acc += fabsf(xp[k] - w[k]);
            bh1[c * 50 + p] = fmaxf(fmaf(-acc, __ldg(g_a1 + c), __ldg(g_b1 + c)), 0.f);
        }
    }
    __syncwarp();

    // pre2: 10ch x 14pos, 5cin x K=9, stride 3
    #pragma unroll 1
    for (int r = 0; r < 5; r++) {
        int idx = lane + 32 * r;
        if (idx < 140) {
            int c = idx / 14, p = idx - 14 * c;
            const float* hp = bh1 + 3 * p;
            float acc = 0.f;
            #pragma unroll
            for (int ci = 0; ci < 5; ci++) {
                float w[12];
                const float* wb = s_small + W2OFF + (c * 5 + ci) * 12;
                ld4(w, wb); ld4(w + 4, wb + 4); ld4(w + 8, wb + 8);
                const float* hc = hp + ci * 50;
                #pragma unroll
                for (int k = 0; k < 9; k++) acc += fabsf(hc[k] - w[k]);
            }
            bh2[c * 14 + p] = fmaxf(fmaf(-acc, __ldg(g_a2 + c), __ldg(g_b2 + c)), 0.f);
        }
    }
    __syncwarp();

    // r1 (writes t over dead x region)
    #pragma unroll 1
    for (int r = 0; r < 5; r++) {
        int idx = lane + 32 * r;
        if (idx < 140) {
            int c = idx / 14, p = idx - 14 * c;
            float w[12];
            const float* wb = s_small + R1OFF + c * 12;
            ld4(w, wb); ld4(w + 4, wb + 4); ld4(w + 8, wb + 8);
            float acc = 0.f;
            #pragma unroll
            for (int ci = 0; ci < 10; ci++) acc += fabsf(bh2[ci * 14 + p] - w[ci]);
            bt[c * 14 + p] = fmaxf(fmaf(-acc, __ldg(g_ar1 + c), __ldg(g_br1 + c)), 0.f);
        }
    }
    __syncwarp();

    // r2 + residual
    #pragma unroll 1
    for (int r = 0; r < 5; r++) {
        int idx = lane + 32 * r;
        if (idx < 140) {
            int c = idx / 14, p = idx - 14 * c;
            float w[12];
            const float* wb = s_small + R2OFF + c * 12;
            ld4(w, wb); ld4(w + 4, wb + 4); ld4(w + 8, wb + 8);
            float acc = 0.f;
            #pragma unroll
            for (int ci = 0; ci < 10; ci++) acc += fabsf(bt[ci * 14 + p] - w[ci]);
            float u = fmaf(-acc, __ldg(g_ar2 + c), __ldg(g_br2 + c));
            fout[c * 14 + p] = fmaxf(u + bh2[c * 14 + p], 0.f);
        }
    }
    // pad f[140:144) so vec4 tails are harmless (weights there are 0 -> |0-0|=0)
    if (lane < 4) fout[140 + lane] = 0.f;
    __syncwarp();
}

__global__ void __launch_bounds__(256) taunet_main(const float* __restrict__ x,
                                                   float* __restrict__ out, int nB)
{
    __shared__ __align__(16) float s_small[SMALL_N];
    __shared__ __align__(16) float s_ws[8][WS_N];

    for (int i = threadIdx.x; i < SMALL_N; i += 256) s_small[i] = g_small[i];
    __syncthreads();

    const int warp = threadIdx.x >> 5, lane = threadIdx.x & 31;
    float* ws = s_ws[warp];

    // ---- per-lane o-layer slot precompute ----
    const int j2 = lane + 64, j3 = lane + 96;
    const int j4 = (lane + 128 < 140) ? lane + 128 : 139;
    const int oa0 = lane;
    const int oa1 = lane + 32;
    const int oa2 = (j2 < 70) ? j2 : (2450 + (j2 - 70));
    const int oa3 = 2450 + (j3 - 70);
    const int oa4 = 2450 + (j4 - 70);
    const int d2 = (j2 < 70) ? j2 : (72 + (j2 - 70));
    const int d3 = 72 + (j3 - 70);
    const int d4 = 72 + (j4 - 70);
    const int jb1 = (lane + 32 < 60) ? lane + 32 : 59;
    const int obb0 = lane / 30, obc0 = lane - 30 * obb0;
    const int ob0 = obb0 * 540 + obc0;
    const int ob1 = 540 + (jb1 - 30);

    const int nPairs = (nB + 1) >> 1;
    const int gw = blockIdx.x * 8 + warp;
    const int stride = gridDim.x * 8;

    for (int p = gw; p < nPairs; p += stride) {
        const int e0 = 2 * p;
        const int e1r = 2 * p + 1;
        const bool e1ok = (e1r < nB);
        const int e1 = e1ok ? e1r : e0;

        early_phase(x + (size_t)e0 * 256, ws, ws + F0OFF, s_small, lane);
        early_phase(x + (size_t)e1 * 256, ws, ws + F1OFF, s_small, lane);

        // ---- oa: both branches + both elements fused ----
        {
            float a00 = 0.f, a01 = 0.f, a02 = 0.f, a03 = 0.f, a04 = 0.f;
            float a10 = 0.f, a11 = 0.f, a12 = 0.f, a13 = 0.f, a14 = 0.f;
            const float4* QA = (const float4*)g_qoa;
            const float4* fp0 = (const float4*)(ws + F0OFF);
            const float4* fp1 = (const float4*)(ws + F1OFF);
            #pragma unroll 5
            for (int i4 = 0; i4 < 35; i4++) {
                float4 f0v = fp0[i4];
                float4 f1v = fp1[i4];
                const float4* q = QA + i4 * 70;
                float4 w;
                w = __ldg(q + oa0); a00 += l1d4(f0v, w); a10 += l1d4(f1v, w);
                w = __ldg(q + oa1); a01 += l1d4(f0v, w); a11 += l1d4(f1v, w);
                w = __ldg(q + oa2); a02 += l1d4(f0v, w); a12 += l1d4(f1v, w);
                w = __ldg(q + oa3); a03 += l1d4(f0v, w); a13 += l1d4(f1v, w);
                w = __ldg(q + oa4); a04 += l1d4(f0v, w); a14 += l1d4(f1v, w);
            }
            float al0 = __ldg(g_aoa + lane),      be0 = __ldg(g_boa + lane);
            float al1 = __ldg(g_aoa + lane + 32), be1 = __ldg(g_boa + lane + 32);
            float al2 = __ldg(g_aoa + j2),        be2 = __ldg(g_boa + j2);
            float al3 = __ldg(g_aoa + j3),        be3 = __ldg(g_boa + j3);
            float al4 = __ldg(g_aoa + j4),        be4 = __ldg(g_boa + j4);
            __syncwarp();   // f reads done before overwriting a region
            float* pa0 = ws + A0OFF;
            float* pa1 = ws + A1OFF;
            pa0[lane]      = fmaxf(fmaf(-a00, al0, be0), 0.f);
            pa0[lane + 32] = fmaxf(fmaf(-a01, al1, be1), 0.f);
            pa0[d2]        = fmaxf(fmaf(-a02, al2, be2), 0.f);
            pa0[d3]        = fmaxf(fmaf(-a03, al3, be3), 0.f);
            pa0[d4]        = fmaxf(fmaf(-a04, al4, be4), 0.f);
            pa1[lane]      = fmaxf(fmaf(-a10, al0, be0), 0.f);
            pa1[lane + 32] = fmaxf(fmaf(-a11, al1, be1), 0.f);
            pa1[d2]        = fmaxf(fmaf(-a12, al2, be2), 0.f);
            pa1[d3]        = fmaxf(fmaf(-a13, al3, be3), 0.f);
            pa1[d4]        = fmaxf(fmaf(-a14, al4, be4), 0.f);
            if (lane < 2) {
                pa0[70 + lane] = 0.f; pa0[142 + lane] = 0.f;
                pa1[70 + lane] = 0.f; pa1[142 + lane] = 0.f;
            }
        }
        __syncwarp();

        // ---- ob: both branches + both elements ----
        {
            float b00 = 0.f, b01 = 0.f, b10 = 0.f, b11 = 0.f;
            const float4* QB = (const float4*)g_qob;
            const float* p00 = ws + A0OFF + obb0 * 72;
            const float* p01 = ws + A0OFF + 72;
            const float* p10 = ws + A1OFF + obb0 * 72;
            const float* p11 = ws + A1OFF + 72;
            #pragma unroll 6
            for (int i4 = 0; i4 < 18; i4++) {
                float4 v00 = *(const float4*)(p00 + 4 * i4);
                float4 v01 = *(const float4*)(p01 + 4 * i4);
                float4 v10 = *(const float4*)(p10 + 4 * i4);
                float4 v11 = *(const float4*)(p11 + 4 * i4);
                const float4* q = QB + i4 * 30;
                float4 w;
                w = __ldg(q + ob0); b00 += l1d4(v00, w); b10 += l1d4(v10, w);
                w = __ldg(q + ob1); b01 += l1d4(v01, w); b11 += l1d4(v11, w);
            }
            float al0 = __ldg(g_aob + lane), be0 = __ldg(g_bob + lane);
            float al1 = __ldg(g_aob + jb1),  be1 = __ldg(g_bob + jb1);
            __syncwarp();
            float* pb0 = ws + B0OFF;
            float* pb1 = ws + B1OFF;
            pb0[obb0 * 32 + obc0] = fmaxf(fmaf(-b00, al0, be0), 0.f);
            pb0[32 + (jb1 - 30)]  = fmaxf(fmaf(-b01, al1, be1), 0.f);
            pb1[obb0 * 32 + obc0] = fmaxf(fmaf(-b10, al0, be0), 0.f);
            pb1[32 + (jb1 - 30)]  = fmaxf(fmaf(-b11, al1, be1), 0.f);
            if (lane < 2) {
                pb0[30 + lane] = 0.f; pb0[62 + lane] = 0.f;
                pb1[30 + lane] = 0.f; pb1[62 + lane] = 0.f;
            }
        }
        __syncwarp();

        // ---- oc ----
        {
            float w0 = __ldg(g_qoc + lane), w1 = __ldg(g_qoc + 32 + lane);
            const float* pb0 = ws + B0OFF;
            const float* pb1 = ws + B1OFF;
            float v00 = fabsf(pb0[lane]      - w0);
            float v01 = fabsf(pb0[32 + lane] - w1);
            float v10 = fabsf(pb1[lane]      - w0);
            float v11 = fabsf(pb1[32 + lane] - w1);
            #pragma unroll
            for (int s = 16; s > 0; s >>= 1) {
                v00 += __shfl_xor_sync(0xffffffffu, v00, s);
                v01 += __shfl_xor_sync(0xffffffffu, v01, s);
                v10 += __shfl_xor_sync(0xffffffffu, v10, s);
                v11 += __shfl_xor_sync(0xffffffffu, v11, s);
            }
            if (lane == 0) {
                float a0 = g_aoc[0], b0 = g_boc[0];
                float a1 = g_aoc[1], b1 = g_boc[1];
                out[e0]      = fmaxf(fmaf(-v00, a0, b0), 0.f);
                out[nB + e0] = fmaxf(fmaf(-v01, a1, b1), 0.f);
                if (e1ok) {
                    out[e1r]      = fmaxf(fmaf(-v10, a0, b0), 0.f);
                    out[nB + e1r] = fmaxf(fmaf(-v11, a1, b1), 0.f);
                }
            }
        }
        __syncwarp();
    }
}

// ---------------------------------------------------------------------------
extern "C" void kernel_launch(void* const* d_in, const int* in_sizes, int n_in,
                              void* d_out, int out_size)
{
    const float* x     = (const float*)d_in[0];
    const float* w1    = (const float*)d_in[1];
    const float* bn1   = (const float*)d_in[2];
    const float* w2    = (const float*)d_in[3];
    const float* bn2   = (const float*)d_in[4];
    const float* wr1   = (const float*)d_in[5];
    const float* bnr1  = (const float*)d_in[6];
    const float* wr2   = (const float*)d_in[7];
    const float* bnr2  = (const float*)d_in[8];
    const float* wo1a  = (const float*)d_in[9];
    const float* bno1a = (const float*)d_in[10];
    const float* wo1b  = (const float*)d_in[11];
    const float* bno1b = (const float*)d_in[12];
    const float* wo1c  = (const float*)d_in[13];
    const float* bno1c = (const float*)d_in[14];
    const float* wo2a  = (const float*)d_in[15];
    const float* bno2a = (const float*)d_in[16];
    const float* wo2b  = (const float*)d_in[17];
    const float* bno2b = (const float*)d_in[18];
    const float* wo2c  = (const float*)d_in[19];
    const float* bno2c = (const float*)d_in[20];

    const int nB = in_sizes[0] / 256;

    setup_kernel<<<11, 256>>>(w1, w2, wr1, wr2, wo1a, wo1b, wo1c, wo2a, wo2b, wo2c,
                              bn1, bn2, bnr1, bnr2, bno1a, bno1b, bno1c,
                              bno2a, bno2b, bno2c);
    taunet_main<<<512, 256>>>(x, (float*)d_out, nB);
}

// round 3
// speedup vs baseline: 2.4968x; 1.1704x over previous
#include <cuda_runtime.h>

// ============================================================================
// AdderNet TauNet R3: pair-packed (float2) early phase, E=4 o-layers.
// ============================================================================

#define EPSV 1e-5f

// ---- s_small layout (floats) ----
#define W1OFF  0
#define W2OFF  80
#define R1OFF  680
#define R2OFF  800
#define A1OFF  920
#define B1OFF  925
#define A2OFF  930
#define B2OFF  940
#define AR1OFF 950
#define BR1OFF 960
#define AR2OFF 970
#define BR2OFF 980
#define AOAOFF 990
#define BOAOFF 1130
#define AOBOFF 1270
#define BOBOFF 1330
#define AOCOFF 1390
#define BOCOFF 1392
#define QOCOFF 1400
#define SMALL_N 1464

__device__ float g_small[1472];
__device__ float g_qoa[2 * 35 * 70 * 4];   // [branch][i/4][c][4]
__device__ float g_qob[2 * 18 * 30 * 4];

__device__ __forceinline__ float quantv(float w, float s) {
    float t = fminf(fmaxf(w / s, -127.f), 127.f);
    return rintf(t) * s;
}

__device__ __forceinline__ void fill_bn(const float* bn, int c, float* A, float* Bt) {
    for (int i = threadIdx.x; i < c; i += blockDim.x) {
        float g = bn[i], b = bn[c + i], m = bn[2 * c + i], v = bn[3 * c + i];
        float al = g * rsqrtf(v + EPSV);
        A[i] = al;
        Bt[i] = b - m * al;
    }
}

// ---------------------------------------------------------------------------
__global__ void setup_kernel(
    const float* __restrict__ w1,   const float* __restrict__ w2,
    const float* __restrict__ wr1,  const float* __restrict__ wr2,
    const float* __restrict__ wo1a, const float* __restrict__ wo1b, const float* __restrict__ wo1c,
    const float* __restrict__ wo2a, const float* __restrict__ wo2b, const float* __restrict__ wo2c,
    const float* __restrict__ bn1,  const float* __restrict__ bn2,
    const float* __restrict__ bnr1, const float* __restrict__ bnr2,
    const float* __restrict__ bno1a, const float* __restrict__ bno1b, const float* __restrict__ bno1c,
    const float* __restrict__ bno2a, const float* __restrict__ bno2b, const float* __restrict__ bno2c)
{
    const int blk = blockIdx.x, tid = threadIdx.x;
    if (blk < 10) {
        const float* w; int n;
        switch (blk) {
            case 0: w = w1;   n = 65;   break;
            case 1: w = w2;   n = 450;  break;
            case 2: w = wr1;  n = 100;  break;
            case 3: w = wr2;  n = 100;  break;
            case 4: w = wo1a; n = 9800; break;
            case 5: w = wo2a; n = 9800; break;
            case 6: w = wo1b; n = 2100; break;
            case 7: w = wo2b; n = 2100; break;
            case 8: w = wo1c; n = 30;   break;
            default: w = wo2c; n = 30;  break;
        }
        __shared__ float red[256];
        float m = 0.f;
        for (int i = tid; i < n; i += 256) m = fmaxf(m, fabsf(w[i]));
        red[tid] = m;
        __syncthreads();
        for (int s = 128; s > 0; s >>= 1) {
            if (tid < s) red[tid] = fmaxf(red[tid], red[tid + s]);
            __syncthreads();
        }
        const float s = red[0] / 127.f;

        if (blk == 0) {
            for (int j = tid; j < 80; j += 256) {
                int c = j >> 4, k = j & 15;
                g_small[W1OFF + j] = (k < 13) ? quantv(w[c * 13 + k], s) : 0.f;
            }
        } else if (blk == 1) {
            for (int j = tid; j < 600; j += 256) {
                int row = j / 12, k = j - row * 12;
                g_small[W2OFF + j] = (k < 9) ? quantv(w[row * 9 + k], s) : 0.f;
            }
        } else if (blk == 2 || blk == 3) {
            float* dst = g_small + (blk == 2 ? R1OFF : R2OFF);
            for (int j = tid; j < 120; j += 256) {
                int c = j / 12, k = j - c * 12;
                dst[j] = (k < 10) ? quantv(w[c * 10 + k], s) : 0.f;
            }
        } else if (blk == 4 || blk == 5) {
            float* dst = g_qoa + (blk - 4) * 9800;
            for (int j = tid; j < 9800; j += 256) {
                int i4 = j / 280, rem = j - i4 * 280;
                int c = rem >> 2, t = rem & 3;
                dst[j] = quantv(w[c * 140 + i4 * 4 + t], s);
            }
        } else if (blk == 6 || blk == 7) {
            float* dst = g_qob + (blk - 6) * 2160;
            for (int j = tid; j < 2160; j += 256) {
                int i4 = j / 120, rem = j - i4 * 120;
                int c = rem >> 2, t = rem & 3;
                int i = i4 * 4 + t;
                dst[j] = (i < 70) ? quantv(w[c * 70 + i], s) : 0.f;
            }
        } else {
            float* dst = g_small + QOCOFF + (blk - 8) * 32;
            if (tid < 32) dst[tid] = (tid < 30) ? quantv(w[tid], s) : 0.f;
        }
    } else {
        fill_bn(bn1, 5,  g_small + A1OFF,  g_small + B1OFF);
        fill_bn(bn2, 10, g_small + A2OFF,  g_small + B2OFF);
        fill_bn(bnr1, 10, g_small + AR1OFF, g_small + BR1OFF);
        fill_bn(bnr2, 10, g_small + AR2OFF, g_small + BR2OFF);
        fill_bn(bno1a, 70, g_small + AOAOFF,      g_small + BOAOFF);
        fill_bn(bno2a, 70, g_small + AOAOFF + 70, g_small + BOAOFF + 70);
        fill_bn(bno1b, 30, g_small + AOBOFF,      g_small + BOBOFF);
        fill_bn(bno2b, 30, g_small + AOBOFF + 30, g_small + BOBOFF + 30);
        fill_bn(bno1c, 1, g_small + AOCOFF,     g_small + BOCOFF);
        fill_bn(bno2c, 1, g_small + AOCOFF + 1, g_small + BOCOFF + 1);
    }
}

// ---------------------------------------------------------------------------
// Per-warp scratch (floats). All activations packed float2 = (elemA, elemB).
//   X   @0     float2[256]  (512)   [T aliases X; A01/A23 alias X+H1 later]
//   H1  @512   float2[250]  (500)
//   H2  @1012  float2[140]  (280)   [B01/B23 alias H2 later]
//   F01 @1292  float2[144]  (288)
//   F23 @1580  float2[144]  (288)
#define XOFF   0
#define H1OFF  512
#define H2OFF  1012
#define F01OFF 1292
#define F23OFF 1580
#define WS_N   1872
#define AA01   0
#define AA23   288
#define BB01   1012
#define BB23   1140

__device__ __forceinline__ void ld4(float* d, const float* s) {
    float4 v = *(const float4*)s;
    d[0] = v.x; d[1] = v.y; d[2] = v.z; d[3] = v.w;
}

__device__ __forceinline__ float l1d4(float4 a, float4 w) {
    return (fabsf(a.x - w.x) + fabsf(a.y - w.y)) + (fabsf(a.z - w.z) + fabsf(a.w - w.w));
}

// early phase for a PAIR of elements, activations float2-packed.
__device__ __noinline__ void early2(const float* __restrict__ xe0,
                                    const float* __restrict__ xe1,
                                    float* ws, const float* s_small,
                                    int lane, int foutOff)
{
    float2* X  = (float2*)(ws + XOFF);
    float2* H1 = (float2*)(ws + H1OFF);
    float2* H2 = (float2*)(ws + H2OFF);
    float2* T  = (float2*)(ws + XOFF);   // aliases X (dead after pre1)
    float2* F  = (float2*)(ws + foutOff);

    // interleave-load x rows: 4 LDG.128 + 4 STS.128
    {
        float4* X4 = (float4*)X;
        #pragma unroll
        for (int i = 0; i < 2; i++) {
            int m = lane + 32 * i;
            float4 a = __ldg((const float4*)xe0 + m);
            float4 b = __ldg((const float4*)xe1 + m);
            X4[2 * m]     = make_float4(a.x, b.x, a.y, b.y);
            X4[2 * m + 1] = make_float4(a.z, b.z, a.w, b.w);
        }
    }
    __syncwarp();

    // pre1: 5ch x 49pos, K=13, stride 5
    #pragma unroll 1
    for (int r = 0; r < 8; r++) {
        int idx = lane + 32 * r;
        if (idx < 245) {
            int c = idx / 49, p = idx - 49 * c;
            float w[16];
            const float* wb = s_small + W1OFF + c * 16;
            ld4(w, wb); ld4(w + 4, wb + 4); ld4(w + 8, wb + 8); ld4(w + 12, wb + 12);
            const float2* xp = X + 5 * p;
            float a0 = 0.f, a1 = 0.f;
            #pragma unroll
            for (int k = 0; k < 13; k++) {
                float2 v = xp[k];
                a0 += fabsf(v.x - w[k]);
                a1 += fabsf(v.y - w[k]);
            }
            float al = s_small[A1OFF + c], be = s_small[B1OFF + c];
            H1[c * 50 + p] = make_float2(fmaxf(fmaf(-a0, al, be), 0.f),
                                         fmaxf(fmaf(-a1, al, be), 0.f));
        }
    }
    __syncwarp();

    // pre2: 10ch x 14pos, 5cin x K=9, stride 3
    #pragma unroll 1
    for (int r = 0; r < 5; r++) {
        int idx = lane + 32 * r;
        if (idx < 140) {
            int c = idx / 14, p = idx - 14 * c;
            const float2* hp = H1 + 3 * p;
            float a0 = 0.f, a1 = 0.f;
            #pragma unroll
            for (int ci = 0; ci < 5; ci++) {
                float w[12];
                const float* wb = s_small + W2OFF + (c * 5 + ci) * 12;
                ld4(w, wb); ld4(w + 4, wb + 4); ld4(w + 8, wb + 8);
                const float2* hc = hp + ci * 50;
                #pragma unroll
                for (int k = 0; k < 9; k++) {
                    float2 v = hc[k];
                    a0 += fabsf(v.x - w[k]);
                    a1 += fabsf(v.y - w[k]);
                }
            }
            float al = s_small[A2OFF + c], be = s_small[B2OFF + c];
            H2[c * 14 + p] = make_float2(fmaxf(fmaf(-a0, al, be), 0.f),
                                         fmaxf(fmaf(-a1, al, be), 0.f));
        }
    }
    __syncwarp();

    // r1
    #pragma unroll 1
    for (int r = 0; r < 5; r++) {
        int idx = lane + 32 * r;
        if (idx < 140) {
            int c = idx / 14, p = idx - 14 * c;
            float w[12];
            const float* wb = s_small + R1OFF + c * 12;
            ld4(w, wb); ld4(w + 4, wb + 4); ld4(w + 8, wb + 8);
            float a0 = 0.f, a1 = 0.f;
            #pragma unroll
            for (int ci = 0; ci < 10; ci++) {
                float2 v = H2[ci * 14 + p];
                a0 += fabsf(v.x - w[ci]);
                a1 += fabsf(v.y - w[ci]);
            }
            float al = s_small[AR1OFF + c], be = s_small[BR1OFF + c];
            T[c * 14 + p] = make_float2(fmaxf(fmaf(-a0, al, be), 0.f),
                                        fmaxf(fmaf(-a1, al, be), 0.f));
        }
    }
    __syncwarp();

    // r2 + residual
    #pragma unroll 1
    for (int r = 0; r < 5; r++) {
        int idx = lane + 32 * r;
        if (idx < 140) {
            int c = idx / 14, p = idx - 14 * c;
            float w[12];
            const float* wb = s_small + R2OFF + c * 12;
            ld4(w, wb); ld4(w + 4, wb + 4); ld4(w + 8, wb + 8);
            float a0 = 0.f, a1 = 0.f;
            #pragma unroll
            for (int ci = 0; ci < 10; ci++) {
                float2 v = T[ci * 14 + p];
                a0 += fabsf(v.x - w[ci]);
                a1 += fabsf(v.y - w[ci]);
            }
            float al = s_small[AR2OFF + c], be = s_small[BR2OFF + c];
            float2 h2v = H2[c * 14 + p];
            F[c * 14 + p] = make_float2(fmaxf(fmaf(-a0, al, be) + h2v.x, 0.f),
                                        fmaxf(fmaf(-a1, al, be) + h2v.y, 0.f));
        }
    }
    if (lane < 4) F[140 + lane] = make_float2(0.f, 0.f);
    __syncwarp();
}

// ---------------------------------------------------------------------------
__global__ void __launch_bounds__(128) taunet_main(const float* __restrict__ x,
                                                   float* __restrict__ out, int nB)
{
    __shared__ __align__(16) float s_small[SMALL_N];
    __shared__ __align__(16) float s_ws[4][WS_N];

    for (int i = threadIdx.x; i < SMALL_N; i += 128) s_small[i] = g_small[i];
    __syncthreads();

    const int warp = threadIdx.x >> 5, lane = threadIdx.x & 31;
    float* ws = s_ws[warp];

    // ---- per-lane o-layer slot precompute ----
    const int j2 = lane + 64, j3 = lane + 96;
    const int j4 = (lane + 128 < 140) ? lane + 128 : 139;
    const int oa0 = lane;
    const int oa1 = lane + 32;
    const int oa2 = (j2 < 70) ? j2 : (2450 + (j2 - 70));
    const int oa3 = 2450 + (j3 - 70);
    const int oa4 = 2450 + (j4 - 70);
    const int d2 = (j2 < 70) ? j2 : (72 + (j2 - 70));
    const int d3 = 72 + (j3 - 70);
    const int d4 = 72 + (j4 - 70);
    const int jb1 = (lane + 32 < 60) ? lane + 32 : 59;
    const int obb0 = lane / 30, obc0 = lane - 30 * obb0;
    const int ob0 = obb0 * 540 + obc0;
    const int ob1 = 540 + (jb1 - 30);

    const int nQ = (nB + 3) >> 2;
    const int gw = blockIdx.x * 4 + warp;
    const int stride = gridDim.x * 4;

    for (int q = gw; q < nQ; q += stride) {
        const int e0 = 4 * q;
        const int e1 = (e0 + 1 < nB) ? e0 + 1 : nB - 1;
        const int e2 = (e0 + 2 < nB) ? e0 + 2 : nB - 1;
        const int e3 = (e0 + 3 < nB) ? e0 + 3 : nB - 1;

        early2(x + (size_t)e0 * 256, x + (size_t)e1 * 256, ws, s_small, lane, F01OFF);
        early2(x + (size_t)e2 * 256, x + (size_t)e3 * 256, ws, s_small, lane, F23OFF);

        // ---- oa: 5 channel slots x 4 elements, weights via LDG.128 ----
        {
            float acc[5][4];
            #pragma unroll
            for (int s = 0; s < 5; s++)
                #pragma unroll
                for (int e = 0; e < 4; e++) acc[s][e] = 0.f;

            const int slots[5] = {oa0, oa1, oa2, oa3, oa4};
            const float4* QA = (const float4*)g_qoa;
            const float4* Fa = (const float4*)(ws + F01OFF);
            const float4* Fb = (const float4*)(ws + F23OFF);

            #pragma unroll 5
            for (int i4 = 0; i4 < 35; i4++) {
                float4 u0 = Fa[2 * i4], u1 = Fa[2 * i4 + 1];
                float4 u2 = Fb[2 * i4], u3 = Fb[2 * i4 + 1];
                float4 fe[4];
                fe[0] = make_float4(u0.x, u0.z, u1.x, u1.z);
                fe[1] = make_float4(u0.y, u0.w, u1.y, u1.w);
                fe[2] = make_float4(u2.x, u2.z, u3.x, u3.z);
                fe[3] = make_float4(u2.y, u2.w, u3.y, u3.w);
                const float4* qrow = QA + i4 * 70;
                #pragma unroll
                for (int s = 0; s < 5; s++) {
                    float4 w = __ldg(qrow + slots[s]);
                    acc[s][0] += l1d4(fe[0], w);
                    acc[s][1] += l1d4(fe[1], w);
                    acc[s][2] += l1d4(fe[2], w);
                    acc[s][3] += l1d4(fe[3], w);
                }
            }
            __syncwarp();   // all F reads done before A overwrite of X/H1 region

            float2* A01 = (float2*)(ws + AA01);
            float2* A23 = (float2*)(ws + AA23);
            const int js[5] = {lane, lane + 32, j2, j3, j4};
            const int ds[5] = {lane, lane + 32, d2, d3, d4};
            #pragma unroll
            for (int s = 0; s < 5; s++) {
                float al = s_small[AOAOFF + js[s]], be = s_small[BOAOFF + js[s]];
                A01[ds[s]] = make_float2(fmaxf(fmaf(-acc[s][0], al, be), 0.f),
                                         fmaxf(fmaf(-acc[s][1], al, be), 0.f));
                A23[ds[s]] = make_float2(fmaxf(fmaf(-acc[s][2], al, be), 0.f),
                                         fmaxf(fmaf(-acc[s][3], al, be), 0.f));
            }
            if (lane < 2) {
                A01[70 + lane] = make_float2(0.f, 0.f);
                A01[142 + lane] = make_float2(0.f, 0.f);
                A23[70 + lane] = make_float2(0.f, 0.f);
                A23[142 + lane] = make_float2(0.f, 0.f);
            }
        }
        __syncwarp();

        // ---- ob: 2 channel slots x 4 elements ----
        {
            float b0[4] = {0.f, 0.f, 0.f, 0.f};
            float b1[4] = {0.f, 0.f, 0.f, 0.f};
            const float4* QB = (const float4*)g_qob;
            const float4* A01_4 = (const float4*)(ws + AA01);
            const float4* A23_4 = (const float4*)(ws + AA23);
            const int m0 = obb0 * 36;   // slot0 branch base (float4 units)

            #pragma unroll 3
            for (int i4 = 0; i4 < 18; i4++) {
                // slot 0 activations (branch obb0)
                float4 v0 = A01_4[m0 + 2 * i4], v1 = A01_4[m0 + 2 * i4 + 1];
                float4 v2 = A23_4[m0 + 2 * i4], v3 = A23_4[m0 + 2 * i4 + 1];
                float4 w0 = __ldg(QB + i4 * 30 + ob0);
                b0[0] += l1d4(make_float4(v0.x, v0.z, v1.x, v1.z), w0);
                b0[1] += l1d4(make_float4(v0.y, v0.w, v1.y, v1.w), w0);
                b0[2] += l1d4(make_float4(v2.x, v2.z, v3.x, v3.z), w0);
                b0[3] += l1d4(make_float4(v2.y, v2.w, v3.y, v3.w), w0);
                // slot 1 activations (branch 1)
                float4 y0 = A01_4[36 + 2 * i4], y1 = A01_4[36 + 2 * i4 + 1];
                float4 y2 = A23_4[36 + 2 * i4], y3 = A23_4[36 + 2 * i4 + 1];
                float4 w1 = __ldg(QB + i4 * 30 + ob1);
                b1[0] += l1d4(make_float4(y0.x, y0.z, y1.x, y1.z), w1);
                b1[1] += l1d4(make_float4(y0.y, y0.w, y1.y, y1.w), w1);
                b1[2] += l1d4(make_float4(y2.x, y2.z, y3.x, y3.z), w1);
                b1[3] += l1d4(make_float4(y2.y, y2.w, y3.y, y3.w), w1);
            }
            __syncwarp();   // A reads done before B overwrite of H2 region

            float2* B01 = (float2*)(ws + BB01);
            float2* B23 = (float2*)(ws + BB23);
            {
                float al = s_small[AOBOFF + lane], be = s_small[BOBOFF + lane];
                B01[obb0 * 32 + obc0] = make_float2(fmaxf(fmaf(-b0[0], al, be), 0.f),
                                                    fmaxf(fmaf(-b0[1], al, be), 0.f));
                B23[obb0 * 32 + obc0] = make_float2(fmaxf(fmaf(-b0[2], al, be), 0.f),
                                                    fmaxf(fmaf(-b0[3], al, be), 0.f));
            }
            {
                float al = s_small[AOBOFF + jb1], be = s_small[BOBOFF + jb1];
                B01[32 + (jb1 - 30)] = make_float2(fmaxf(fmaf(-b1[0], al, be), 0.f),
                                                   fmaxf(fmaf(-b1[1], al, be), 0.f));
                B23[32 + (jb1 - 30)] = make_float2(fmaxf(fmaf(-b1[2], al, be), 0.f),
                                                   fmaxf(fmaf(-b1[3], al, be), 0.f));
            }
            if (lane < 2) {
                B01[30 + lane] = make_float2(0.f, 0.f);
                B01[62 + lane] = make_float2(0.f, 0.f);
                B23[30 + lane] = make_float2(0.f, 0.f);
                B23[62 + lane] = make_float2(0.f, 0.f);
            }
        }
        __syncwarp();

        // ---- oc: 8 reductions (4 elems x 2 branches) ----
        {
            const float2* B01 = (const float2*)(ws + BB01);
            const float2* B23 = (const float2*)(ws + BB23);
            float w0 = s_small[QOCOFF + lane], w1 = s_small[QOCOFF + 32 + lane];
            float2 p0 = B01[lane], p1 = B01[32 + lane];
            float2 p2 = B23[lane], p3 = B23[32 + lane];
            float vA0 = fabsf(p0.x - w0), vA1 = fabsf(p0.y - w0);
            float vA2 = fabsf(p2.x - w0), vA3 = fabsf(p2.y - w0);
            float vI0 = fabsf(p1.x - w1), vI1 = fabsf(p1.y - w1);
            float vI2 = fabsf(p3.x - w1), vI3 = fabsf(p3.y - w1);
            #pragma unroll
            for (int s = 16; s > 0; s >>= 1) {
                vA0 += __shfl_xor_sync(0xffffffffu, vA0, s);
                vA1 += __shfl_xor_sync(0xffffffffu, vA1, s);
                vA2 += __shfl_xor_sync(0xffffffffu, vA2, s);
                vA3 += __shfl_xor_sync(0xffffffffu, vA3, s);
                vI0 += __shfl_xor_sync(0xffffffffu, vI0, s);
                vI1 += __shfl_xor_sync(0xffffffffu, vI1, s);
                vI2 += __shfl_xor_sync(0xffffffffu, vI2, s);
                vI3 += __shfl_xor_sync(0xffffffffu, vI3, s);
            }
            if (lane == 0) {
                float aA = s_small[AOCOFF],     bA = s_small[BOCOFF];
                float aI = s_small[AOCOFF + 1], bI = s_small[BOCOFF + 1];
                float vA[4] = {vA0, vA1, vA2, vA3};
                float vI[4] = {vI0, vI1, vI2, vI3};
                #pragma unroll
                for (int i = 0; i < 4; i++) {
                    if (e0 + i < nB) {
                        out[e0 + i]      = fmaxf(fmaf(-vA[i], aA, bA), 0.f);
                        out[nB + e0 + i] = fmaxf(fmaf(-vI[i], aI, bI), 0.f);
                    }
                }
            }
        }
        __syncwarp();   // B reads done before next iteration's early2 writes
    }
}

// ---------------------------------------------------------------------------
extern "C" void kernel_launch(void* const* d_in, const int* in_sizes, int n_in,
                              void* d_out, int out_size)
{
    const float* x     = (const float*)d_in[0];
    const float* w1    = (const float*)d_in[1];
    const float* bn1   = (const float*)d_in[2];
    const float* w2    = (const float*)d_in[3];
    const float* bn2   = (const float*)d_in[4];
    const float* wr1   = (const float*)d_in[5];
    const float* bnr1  = (const float*)d_in[6];
    const float* wr2   = (const float*)d_in[7];
    const float* bnr2  = (const float*)d_in[8];
    const float* wo1a  = (const float*)d_in[9];
    const float* bno1a = (const float*)d_in[10];
    const float* wo1b  = (const float*)d_in[11];
    const float* bno1b = (const float*)d_in[12];
    const float* wo1c  = (const float*)d_in[13];
    const float* bno1c = (const float*)d_in[14];
    const float* wo2a  = (const float*)d_in[15];
    const float* bno2a = (const float*)d_in[16];
    const float* wo2b  = (const float*)d_in[17];
    const float* bno2b = (const float*)d_in[18];
    const float* wo2c  = (const float*)d_in[19];
    const float* bno2c = (const float*)d_in[20];

    const int nB = in_sizes[0] / 256;

    setup_kernel<<<11, 256>>>(w1, w2, wr1, wr2, wo1a, wo1b, wo1c, wo2a, wo2b, wo2c,
                              bn1, bn2, bnr1, bnr2, bno1a, bno1b, bno1c,
                              bno2a, bno2b, bno2c);
    taunet_main<<<512, 128>>>(x, (float*)d_out, nB);
}

// round 4
// speedup vs baseline: 2.6800x; 1.0734x over previous
#include <cuda_runtime.h>

// ============================================================================
// AdderNet TauNet R4: quad-packed (float4) activations end-to-end.
// ============================================================================

#define EPSV 1e-5f

// ---- s_small layout (floats) ----
#define W1OFF  0
#define W2OFF  80
#define R1OFF  680
#define R2OFF  800
#define A1OFF  920
#define B1OFF  925
#define A2OFF  930
#define B2OFF  940
#define AR1OFF 950
#define BR1OFF 960
#define AR2OFF 970
#define BR2OFF 980
#define AOAOFF 990
#define BOAOFF 1130
#define AOBOFF 1270
#define BOBOFF 1330
#define AOCOFF 1390
#define BOCOFF 1392
#define QOCOFF 1400
#define SMALL_N 1464

__device__ float g_small[1472];
__device__ float g_qoa[2 * 35 * 70 * 4];   // [branch][i/4][c][4]
__device__ float g_qob[2 * 18 * 30 * 4];

__device__ __forceinline__ float quantv(float w, float s) {
    float t = fminf(fmaxf(w / s, -127.f), 127.f);
    return rintf(t) * s;
}

__device__ __forceinline__ void fill_bn(const float* bn, int c, float* A, float* Bt) {
    for (int i = threadIdx.x; i < c; i += blockDim.x) {
        float g = bn[i], b = bn[c + i], m = bn[2 * c + i], v = bn[3 * c + i];
        float al = g * rsqrtf(v + EPSV);
        A[i] = al;
        Bt[i] = b - m * al;
    }
}

// ---------------------------------------------------------------------------
__global__ void setup_kernel(
    const float* __restrict__ w1,   const float* __restrict__ w2,
    const float* __restrict__ wr1,  const float* __restrict__ wr2,
    const float* __restrict__ wo1a, const float* __restrict__ wo1b, const float* __restrict__ wo1c,
    const float* __restrict__ wo2a, const float* __restrict__ wo2b, const float* __restrict__ wo2c,
    const float* __restrict__ bn1,  const float* __restrict__ bn2,
    const float* __restrict__ bnr1, const float* __restrict__ bnr2,
    const float* __restrict__ bno1a, const float* __restrict__ bno1b, const float* __restrict__ bno1c,
    const float* __restrict__ bno2a, const float* __restrict__ bno2b, const float* __restrict__ bno2c)
{
    const int blk = blockIdx.x, tid = threadIdx.x;
    if (blk < 10) {
        const float* w; int n;
        switch (blk) {
            case 0: w = w1;   n = 65;   break;
            case 1: w = w2;   n = 450;  break;
            case 2: w = wr1;  n = 100;  break;
            case 3: w = wr2;  n = 100;  break;
            case 4: w = wo1a; n = 9800; break;
            case 5: w = wo2a; n = 9800; break;
            case 6: w = wo1b; n = 2100; break;
            case 7: w = wo2b; n = 2100; break;
            case 8: w = wo1c; n = 30;   break;
            default: w = wo2c; n = 30;  break;
        }
        __shared__ float red[256];
        float m = 0.f;
        for (int i = tid; i < n; i += 256) m = fmaxf(m, fabsf(w[i]));
        red[tid] = m;
        __syncthreads();
        for (int s = 128; s > 0; s >>= 1) {
            if (tid < s) red[tid] = fmaxf(red[tid], red[tid + s]);
            __syncthreads();
        }
        const float s = red[0] / 127.f;

        if (blk == 0) {
            for (int j = tid; j < 80; j += 256) {
                int c = j >> 4, k = j & 15;
                g_small[W1OFF + j] = (k < 13) ? quantv(w[c * 13 + k], s) : 0.f;
            }
        } else if (blk == 1) {
            for (int j = tid; j < 600; j += 256) {
                int row = j / 12, k = j - row * 12;
                g_small[W2OFF + j] = (k < 9) ? quantv(w[row * 9 + k], s) : 0.f;
            }
        } else if (blk == 2 || blk == 3) {
            float* dst = g_small + (blk == 2 ? R1OFF : R2OFF);
            for (int j = tid; j < 120; j += 256) {
                int c = j / 12, k = j - c * 12;
                dst[j] = (k < 10) ? quantv(w[c * 10 + k], s) : 0.f;
            }
        } else if (blk == 4 || blk == 5) {
            float* dst = g_qoa + (blk - 4) * 9800;
            for (int j = tid; j < 9800; j += 256) {
                int i4 = j / 280, rem = j - i4 * 280;
                int c = rem >> 2, t = rem & 3;
                dst[j] = quantv(w[c * 140 + i4 * 4 + t], s);
            }
        } else if (blk == 6 || blk == 7) {
            float* dst = g_qob + (blk - 6) * 2160;
            for (int j = tid; j < 2160; j += 256) {
                int i4 = j / 120, rem = j - i4 * 120;
                int c = rem >> 2, t = rem & 3;
                int i = i4 * 4 + t;
                dst[j] = (i < 70) ? quantv(w[c * 70 + i], s) : 0.f;
            }
        } else {
            float* dst = g_small + QOCOFF + (blk - 8) * 32;
            if (tid < 32) dst[tid] = (tid < 30) ? quantv(w[tid], s) : 0.f;
        }
    } else {
        fill_bn(bn1, 5,  g_small + A1OFF,  g_small + B1OFF);
        fill_bn(bn2, 10, g_small + A2OFF,  g_small + B2OFF);
        fill_bn(bnr1, 10, g_small + AR1OFF, g_small + BR1OFF);
        fill_bn(bnr2, 10, g_small + AR2OFF, g_small + BR2OFF);
        fill_bn(bno1a, 70, g_small + AOAOFF,      g_small + BOAOFF);
        fill_bn(bno2a, 70, g_small + AOAOFF + 70, g_small + BOAOFF + 70);
        fill_bn(bno1b, 30, g_small + AOBOFF,      g_small + BOBOFF);
        fill_bn(bno2b, 30, g_small + AOBOFF + 30, g_small + BOBOFF + 30);
        fill_bn(bno1c, 1, g_small + AOCOFF,     g_small + BOCOFF);
        fill_bn(bno2c, 1, g_small + AOCOFF + 1, g_small + BOCOFF + 1);
    }
}

// ---------------------------------------------------------------------------
// Per-warp scratch (floats). All activations float4 = (e0,e1,e2,e3).
//   X  @0     float4[256] (1024)   [T aliases X; A aliases X]
//   H1 @1024  float4[250] (1000)   [F aliases H1]
//   H2 @2048  float4[144] (576)    [B aliases H2]
#define XOFF  0
#define H1OFF 1024
#define H2OFF 2048
#define FOFF  1024
#define AOFF  0
#define BOFF  2048
#define WS_N  2624

__device__ __forceinline__ void ld4(float* d, const float* s) {
    float4 v = *(const float4*)s;
    d[0] = v.x; d[1] = v.y; d[2] = v.z; d[3] = v.w;
}

// acc[e] += |u[e] - w| over 4 packed elements
__device__ __forceinline__ void acc4(float4& a, float4 u, float w) {
    a.x += fabsf(u.x - w);
    a.y += fabsf(u.y - w);
    a.z += fabsf(u.z - w);
    a.w += fabsf(u.w - w);
}

__device__ __forceinline__ float4 bnrelu4(float4 a, float al, float be) {
    return make_float4(fmaxf(fmaf(-a.x, al, be), 0.f),
                       fmaxf(fmaf(-a.y, al, be), 0.f),
                       fmaxf(fmaf(-a.z, al, be), 0.f),
                       fmaxf(fmaf(-a.w, al, be), 0.f));
}

__global__ void __launch_bounds__(128) taunet_main(const float* __restrict__ x,
                                                   float* __restrict__ out, int nB)
{
    __shared__ __align__(16) float s_small[SMALL_N];
    __shared__ __align__(16) float s_ws[4][WS_N];

    for (int i = threadIdx.x; i < SMALL_N; i += 128) s_small[i] = g_small[i];
    __syncthreads();

    const int warp = threadIdx.x >> 5, lane = threadIdx.x & 31;
    float* ws = s_ws[warp];
    float4* X4  = (float4*)(ws + XOFF);
    float4* H14 = (float4*)(ws + H1OFF);
    float4* H24 = (float4*)(ws + H2OFF);
    float4* T4  = (float4*)(ws + XOFF);
    float4* F4  = (float4*)(ws + FOFF);
    float4* A4  = (float4*)(ws + AOFF);
    float4* B4  = (float4*)(ws + BOFF);

    // ---- per-lane o-layer slot precompute ----
    const int j2 = lane + 64, j3 = lane + 96;
    const int j4 = (lane + 128 < 140) ? lane + 128 : 139;
    const int oa2 = (j2 < 70) ? j2 : (2450 + (j2 - 70));
    const int oa3 = 2450 + (j3 - 70);
    const int oa4 = 2450 + (j4 - 70);
    const int d2 = (j2 < 70) ? j2 : (72 + (j2 - 70));
    const int d3 = 72 + (j3 - 70);
    const int d4 = 72 + (j4 - 70);
    const int jb1 = (lane + 32 < 60) ? lane + 32 : 59;
    const int obb0 = lane / 30, obc0 = lane - 30 * obb0;
    const int ob0 = obb0 * 540 + obc0;
    const int ob1 = 540 + (jb1 - 30);

    const int nQ = (nB + 3) >> 2;
    const int gw = blockIdx.x * 4 + warp;
    const int stride = gridDim.x * 4;

    for (int q = gw; q < nQ; q += stride) {
        const int e0 = 4 * q;
        const int e1 = (e0 + 1 < nB) ? e0 + 1 : nB - 1;
        const int e2 = (e0 + 2 < nB) ? e0 + 2 : nB - 1;
        const int e3 = (e0 + 3 < nB) ? e0 + 3 : nB - 1;

        // ---- stage 4 input rows, transposed into float4-per-position ----
        {
            const float4* r0 = (const float4*)(x + (size_t)e0 * 256);
            const float4* r1 = (const float4*)(x + (size_t)e1 * 256);
            const float4* r2 = (const float4*)(x + (size_t)e2 * 256);
            const float4* r3 = (const float4*)(x + (size_t)e3 * 256);
            #pragma unroll
            for (int i = 0; i < 2; i++) {
                int m = lane + 32 * i;
                float4 a = __ldg(r0 + m);
                float4 b = __ldg(r1 + m);
                float4 c = __ldg(r2 + m);
                float4 d = __ldg(r3 + m);
                X4[4 * m + 0] = make_float4(a.x, b.x, c.x, d.x);
                X4[4 * m + 1] = make_float4(a.y, b.y, c.y, d.y);
                X4[4 * m + 2] = make_float4(a.z, b.z, c.z, d.z);
                X4[4 * m + 3] = make_float4(a.w, b.w, c.w, d.w);
            }
        }
        __syncwarp();

        // ---- pre1: 5ch x 49pos, K=13, stride 5 ----
        #pragma unroll 1
        for (int r = 0; r < 8; r++) {
            int idx = lane + 32 * r;
            if (idx < 245) {
                int c = idx / 49, p = idx - 49 * c;
                float w[16];
                const float* wb = s_small + W1OFF + c * 16;
                ld4(w, wb); ld4(w + 4, wb + 4); ld4(w + 8, wb + 8); ld4(w + 12, wb + 12);
                const float4* xp = X4 + 5 * p;
                float4 a = make_float4(0.f, 0.f, 0.f, 0.f);
                #pragma unroll
                for (int k = 0; k < 13; k++) acc4(a, xp[k], w[k]);
                H14[c * 50 + p] = bnrelu4(a, s_small[A1OFF + c], s_small[B1OFF + c]);
            }
        }
        __syncwarp();

        // ---- pre2: 10ch x 14pos, 5cin x K=9, stride 3 ----
        #pragma unroll 1
        for (int r = 0; r < 5; r++) {
            int idx = lane + 32 * r;
            if (idx < 140) {
                int c = idx / 14, p = idx - 14 * c;
                const float4* hp = H14 + 3 * p;
                float4 a = make_float4(0.f, 0.f, 0.f, 0.f);
                #pragma unroll
                for (int ci = 0; ci < 5; ci++) {
                    float w[12];
                    const float* wb = s_small + W2OFF + (c * 5 + ci) * 12;
                    ld4(w, wb); ld4(w + 4, wb + 4); ld4(w + 8, wb + 8);
                    const float4* hc = hp + ci * 50;
                    #pragma unroll
                    for (int k = 0; k < 9; k++) acc4(a, hc[k], w[k]);
                }
                H24[c * 14 + p] = bnrelu4(a, s_small[A2OFF + c], s_small[B2OFF + c]);
            }
        }
        __syncwarp();

        // ---- r1 (T over dead X) ----
        #pragma unroll 1
        for (int r = 0; r < 5; r++) {
            int idx = lane + 32 * r;
            if (idx < 140) {
                int c = idx / 14, p = idx - 14 * c;
                float w[12];
                const float* wb = s_small + R1OFF + c * 12;
                ld4(w, wb); ld4(w + 4, wb + 4); ld4(w + 8, wb + 8);
                float4 a = make_float4(0.f, 0.f, 0.f, 0.f);
                #pragma unroll
                for (int ci = 0; ci < 10; ci++) acc4(a, H24[ci * 14 + p], w[ci]);
                T4[c * 14 + p] = bnrelu4(a, s_small[AR1OFF + c], s_small[BR1OFF + c]);
            }
        }
        __syncwarp();

        // ---- r2 + residual (F over dead H1) ----
        #pragma unroll 1
        for (int r = 0; r < 5; r++) {
            int idx = lane + 32 * r;
            if (idx < 140) {
                int c = idx / 14, p = idx - 14 * c;
                float w[12];
                const float* wb = s_small + R2OFF + c * 12;
                ld4(w, wb); ld4(w + 4, wb + 4); ld4(w + 8, wb + 8);
                float4 a = make_float4(0.f, 0.f, 0.f, 0.f);
                #pragma unroll
                for (int ci = 0; ci < 10; ci++) acc4(a, T4[ci * 14 + p], w[ci]);
                float al = s_small[AR2OFF + c], be = s_small[BR2OFF + c];
                float4 h2v = H24[c * 14 + p];
                F4[c * 14 + p] = make_float4(
                    fmaxf(fmaf(-a.x, al, be) + h2v.x, 0.f),
                    fmaxf(fmaf(-a.y, al, be) + h2v.y, 0.f),
                    fmaxf(fmaf(-a.z, al, be) + h2v.z, 0.f),
                    fmaxf(fmaf(-a.w, al, be) + h2v.w, 0.f));
            }
        }
        if (lane < 4) F4[140 + lane] = make_float4(0.f, 0.f, 0.f, 0.f);
        __syncwarp();

        // ---- oa: 5 channel slots x 4 packed elements ----
        {
            float4 acc[5];
            #pragma unroll
            for (int s = 0; s < 5; s++) acc[s] = make_float4(0.f, 0.f, 0.f, 0.f);

            const int slots[5] = {lane, lane + 32, oa2, oa3, oa4};
            const float4* QA = (const float4*)g_qoa;

            #pragma unroll 5
            for (int i4 = 0; i4 < 35; i4++) {
                float4 u0 = F4[4 * i4 + 0];
                float4 u1 = F4[4 * i4 + 1];
                float4 u2 = F4[4 * i4 + 2];
                float4 u3 = F4[4 * i4 + 3];
                const float4* qrow = QA + i4 * 70;
                #pragma unroll
                for (int s = 0; s < 5; s++) {
                    float4 w = __ldg(qrow + slots[s]);
                    acc4(acc[s], u0, w.x);
                    acc4(acc[s], u1, w.y);
                    acc4(acc[s], u2, w.z);
                    acc4(acc[s], u3, w.w);
                }
            }
            __syncwarp();   // F reads done before A overwrite of X region

            const int js[5] = {lane, lane + 32, j2, j3, j4};
            const int ds[5] = {lane, lane + 32, d2, d3, d4};
            #pragma unroll
            for (int s = 0; s < 5; s++) {
                A4[ds[s]] = bnrelu4(acc[s], s_small[AOAOFF + js[s]], s_small[BOAOFF + js[s]]);
            }
            if (lane < 2) {
                A4[70 + lane]  = make_float4(0.f, 0.f, 0.f, 0.f);
                A4[142 + lane] = make_float4(0.f, 0.f, 0.f, 0.f);
            }
        }
        __syncwarp();

        // ---- ob: 2 channel slots x 4 packed elements ----
        {
            float4 b0 = make_float4(0.f, 0.f, 0.f, 0.f);
            float4 b1 = make_float4(0.f, 0.f, 0.f, 0.f);
            const float4* QB = (const float4*)g_qob;
            const float4* a0p = A4 + obb0 * 72;
            const float4* a1p = A4 + 72;

            #pragma unroll 6
            for (int i4 = 0; i4 < 18; i4++) {
                float4 w0 = __ldg(QB + i4 * 30 + ob0);
                acc4(b0, a0p[4 * i4 + 0], w0.x);
                acc4(b0, a0p[4 * i4 + 1], w0.y);
                acc4(b0, a0p[4 * i4 + 2], w0.z);
                acc4(b0, a0p[4 * i4 + 3], w0.w);
                float4 w1 = __ldg(QB + i4 * 30 + ob1);
                acc4(b1, a1p[4 * i4 + 0], w1.x);
                acc4(b1, a1p[4 * i4 + 1], w1.y);
                acc4(b1, a1p[4 * i4 + 2], w1.z);
                acc4(b1, a1p[4 * i4 + 3], w1.w);
            }
            __syncwarp();   // A reads done before B overwrite of H2 region

            B4[obb0 * 32 + obc0] = bnrelu4(b0, s_small[AOBOFF + lane], s_small[BOBOFF + lane]);
            B4[32 + (jb1 - 30)]  = bnrelu4(b1, s_small[AOBOFF + jb1], s_small[BOBOFF + jb1]);
            if (lane < 2) {
                B4[30 + lane] = make_float4(0.f, 0.f, 0.f, 0.f);
                B4[62 + lane] = make_float4(0.f, 0.f, 0.f, 0.f);
            }
        }
        __syncwarp();

        // ---- oc: 8 reductions (4 elems x 2 branches) ----
        {
            float w0 = s_small[QOCOFF + lane], w1 = s_small[QOCOFF + 32 + lane];
            float4 p0 = B4[lane];        // amp branch, 4 elems
            float4 p1 = B4[32 + lane];   // inten branch
            float vA0 = fabsf(p0.x - w0), vA1 = fabsf(p0.y - w0);
            float vA2 = fabsf(p0.z - w0), vA3 = fabsf(p0.w - w0);
            float vI0 = fabsf(p1.x - w1), vI1 = fabsf(p1.y - w1);
            float vI2 = fabsf(p1.z - w1), vI3 = fabsf(p1.w - w1);
            #pragma unroll
            for (int s = 16; s > 0; s >>= 1) {
                vA0 += __shfl_xor_sync(0xffffffffu, vA0, s);
                vA1 += __shfl_xor_sync(0xffffffffu, vA1, s);
                vA2 += __shfl_xor_sync(0xffffffffu, vA2, s);
                vA3 += __shfl_xor_sync(0xffffffffu, vA3, s);
                vI0 += __shfl_xor_sync(0xffffffffu, vI0, s);
                vI1 += __shfl_xor_sync(0xffffffffu, vI1, s);
                vI2 += __shfl_xor_sync(0xffffffffu, vI2, s);
                vI3 += __shfl_xor_sync(0xffffffffu, vI3, s);
            }
            if (lane == 0) {
                float aA = s_small[AOCOFF],     bA = s_small[BOCOFF];
                float aI = s_small[AOCOFF + 1], bI = s_small[BOCOFF + 1];
                float vA[4] = {vA0, vA1, vA2, vA3};
                float vI[4] = {vI0, vI1, vI2, vI3};
                #pragma unroll
                for (int i = 0; i < 4; i++) {
                    if (e0 + i < nB) {
                        out[e0 + i]      = fmaxf(fmaf(-vA[i], aA, bA), 0.f);
                        out[nB + e0 + i] = fmaxf(fmaf(-vI[i], aI, bI), 0.f);
                    }
                }
            }
        }
        __syncwarp();   // B reads done before next iteration overwrites
    }
}

// ---------------------------------------------------------------------------
extern "C" void kernel_launch(void* const* d_in, const int* in_sizes, int n_in,
                              void* d_out, int out_size)
{
    const float* x     = (const float*)d_in[0];
    const float* w1    = (const float*)d_in[1];
    const float* bn1   = (const float*)d_in[2];
    const float* w2    = (const float*)d_in[3];
    const float* bn2   = (const float*)d_in[4];
    const float* wr1   = (const float*)d_in[5];
    const float* bnr1  = (const float*)d_in[6];
    const float* wr2   = (const float*)d_in[7];
    const float* bnr2  = (const float*)d_in[8];
    const float* wo1a  = (const float*)d_in[9];
    const float* bno1a = (const float*)d_in[10];
    const float* wo1b  = (const float*)d_in[11];
    const float* bno1b = (const float*)d_in[12];
    const float* wo1c  = (const float*)d_in[13];
    const float* bno1c = (const float*)d_in[14];
    const float* wo2a  = (const float*)d_in[15];
    const float* bno2a = (const float*)d_in[16];
    const float* wo2b  = (const float*)d_in[17];
    const float* bno2b = (const float*)d_in[18];
    const float* wo2c  = (const float*)d_in[19];
    const float* bno2c = (const float*)d_in[20];

    const int nB = in_sizes[0] / 256;

    setup_kernel<<<11, 256>>>(w1, w2, wr1, wr2, wo1a, wo1b, wo1c, wo2a, wo2b, wo2c,
                              bn1, bn2, bnr1, bnr2, bno1a, bno1b, bno1c,
                              bno2a, bno2b, bno2c);
    taunet_main<<<512, 128>>>(x, (float*)d_out, nB);
}